// round 12
// baseline (speedup 1.0000x reference)
#include <cuda_runtime.h>
#include <cuda_bf16.h>
#include <math.h>
#include <cstdint>

typedef unsigned long long ull;

#define B_ROWS 4096
#define K_COLS 256
#define D_DIM  128
#define BM     128       // x-rows per CTA
#define BKH    32        // hyperplanes per CTA (=> 64 interleaved W rows)
#define THREADS 512
#define MIN_NORM 1e-15f

#define TSTRIDE 136      // bf16 elems per tile row (272 B), conflict-free ldmatrix
#define ROW_BYTES (TSTRIDE * 2)
#define XTILE_BYTES (128 * ROW_BYTES)   // 34816
#define WTILE_BYTES (64  * ROW_BYTES)   // 17408

// smem byte offsets
#define OFF_Y2   0                        // 128 f32 = 512B
#define OFF_KST  512                      // 32 x float4 = 512B
#define OFF_XHI  1024
#define OFF_XLO  (OFF_XHI + XTILE_BYTES)
#define OFF_WHI  (OFF_XLO + XTILE_BYTES)
#define OFF_WLO  (OFF_WHI + WTILE_BYTES)
#define SMEM_BYTES (OFF_WLO + WTILE_BYTES)   // 105472 B -> 2 CTAs/SM

// ---------------------------------------------------------------------------
__device__ __forceinline__ uint32_t smem_u32(const void* p) {
    uint32_t a;
    asm("{ .reg .u64 t; cvta.to.shared.u64 t, %1; cvt.u32.u64 %0, t; }"
        : "=r"(a) : "l"(p));
    return a;
}

__device__ __forceinline__ void ldsm_x4(uint32_t* r, uint32_t addr) {
    asm volatile("ldmatrix.sync.aligned.m8n8.x4.shared.b16 {%0,%1,%2,%3}, [%4];"
                 : "=r"(r[0]), "=r"(r[1]), "=r"(r[2]), "=r"(r[3]) : "r"(addr));
}

__device__ __forceinline__ void mma_bf16(float* c, const uint32_t* a, const uint32_t* b) {
    asm volatile(
        "mma.sync.aligned.m16n8k16.row.col.f32.bf16.bf16.f32 "
        "{%0,%1,%2,%3}, {%4,%5,%6,%7}, {%8,%9}, {%0,%1,%2,%3};"
        : "+f"(c[0]), "+f"(c[1]), "+f"(c[2]), "+f"(c[3])
        : "r"(a[0]), "r"(a[1]), "r"(a[2]), "r"(a[3]), "r"(b[0]), "r"(b[1]));
}

__device__ __forceinline__ uint32_t prmt7632(uint32_t a, uint32_t b) {
    uint32_t r;
    asm("prmt.b32 %0, %1, %2, 0x7632;" : "=r"(r) : "r"(a), "r"(b));
    return r;
}

// truncation-based fp32 -> bf16 hi/lo split (all fixed-lat ALU ops)
__device__ __forceinline__ void cvt4t(const float4 v, uint2& hi, uint2& lo) {
    uint32_t u0 = __float_as_uint(v.x), u1 = __float_as_uint(v.y);
    uint32_t u2 = __float_as_uint(v.z), u3 = __float_as_uint(v.w);
    hi.x = prmt7632(u0, u1);
    hi.y = prmt7632(u2, u3);
    float l0 = v.x - __uint_as_float(u0 & 0xFFFF0000u);
    float l1 = v.y - __uint_as_float(u1 & 0xFFFF0000u);
    float l2 = v.z - __uint_as_float(u2 & 0xFFFF0000u);
    float l3 = v.w - __uint_as_float(u3 & 0xFFFF0000u);
    lo.x = prmt7632(__float_as_uint(l0), __float_as_uint(l1));
    lo.y = prmt7632(__float_as_uint(l2), __float_as_uint(l3));
}

// fast asinh: sign * log(|z| + sqrt(z^2+1))
__device__ __forceinline__ float fast_asinh(float z) {
    float az = fabsf(z);
    float u  = fmaf(az, az, 1.f);
    float t;
    asm("sqrt.approx.f32 %0, %1;" : "=f"(t) : "f"(u));
    float r = __logf(az + t);
    return copysignf(r, z);
}

// single-division Mobius epilogue; kc = {p2, pa, beta, 2an}
__device__ __forceinline__ float mobius_epi(float px, float xa, float y2, float4 kc) {
    const float p2 = kc.x, pa = kc.y, beta = kc.z, an2 = kc.w;
    float t     = fmaf(-2.f, px, 1.f);          // 1 - 2px
    float alpha = t + y2;
    float den   = fmaf(p2, y2, t);              // den_m
    float num   = fmaf(beta, xa, -alpha * pa);  // beta*xa - alpha*pa
    float b2y2  = beta * beta * y2;
    float e1    = alpha * p2;
    float e2    = fmaf(e1, alpha, b2y2);
    float e3    = fmaf(-beta, t, beta);         // 2*beta*px
    float ms2   = fmaf(-alpha, e3, e2);         // alpha^2 p2 - 2ab px + b^2 y2
    float g     = fmaf(den, den, -ms2);
    float dn    = fmaxf(an2 * g, MIN_NORM);
    float z     = __fdividef(4.f * num * den, dn);
    return an2 * fast_asinh(z);
}

// ---------------------------------------------------------------------------
extern __shared__ char smem[];

__global__ void __launch_bounds__(THREADS, 2)
mobius_mlr_mma_kernel(const float* __restrict__ x,
                      const float* __restrict__ gp,
                      const float* __restrict__ ga,
                      float* __restrict__ out) {
    const uint32_t sb  = smem_u32(smem);
    const int tid  = threadIdx.x;
    const int wid  = tid >> 5;
    const int lane = tid & 31;
    const int kb   = blockIdx.x * BKH;
    const int bb   = blockIdx.y * BM;

    float*  y2s = (float*)(smem + OFF_Y2);
    float4* kst = (float4*)(smem + OFF_KST);

    // ---- load X: full rows, warp-per-row (8 iters), 32 regs ---------------
    const float4* x4 = (const float4*)(x + (size_t)bb * D_DIM);
    float4 Xv[8];
#pragma unroll
    for (int i = 0; i < 8; i++) {
        int row = wid + 16 * i;
        Xv[i] = x4[row * 32 + lane];
    }

    // ---- load W: half-warp per row, d-halves (p rows even, a rows odd) ----
    // Wv0[i]: h0 of k=wid+16i ; Wv1[i]: h1. lanes 0-15 p-row, 16-31 a-row.
    float4 Wv0[2], Wv1[2];
#pragma unroll
    for (int i = 0; i < 2; i++) {
        int row = 2 * wid + 32 * i + (lane >> 4);   // 0..63
        int kk  = kb + (row >> 1);
        const float4* src = (const float4*)(((row & 1) ? ga : gp) + (size_t)kk * D_DIM);
        Wv0[i] = src[lane & 15];
        Wv1[i] = src[(lane & 15) + 16];
    }

    // ---- convert X + y2 (full-warp reduce, one row per iter) --------------
#pragma unroll
    for (int i = 0; i < 8; i++) {
        int row = wid + 16 * i;
        uint2 hi, lo;
        cvt4t(Xv[i], hi, lo);
        uint32_t off = (uint32_t)(row * ROW_BYTES + lane * 8);
        *(uint2*)(smem + OFF_XHI + off) = hi;
        *(uint2*)(smem + OFF_XLO + off) = lo;
        float4 v = Xv[i];
        float s = fmaf(v.x, v.x, fmaf(v.y, v.y, fmaf(v.z, v.z, v.w * v.w)));
        s += __shfl_xor_sync(0xffffffffu, s, 1);
        s += __shfl_xor_sync(0xffffffffu, s, 2);
        s += __shfl_xor_sync(0xffffffffu, s, 4);
        s += __shfl_xor_sync(0xffffffffu, s, 8);
        s += __shfl_xor_sync(0xffffffffu, s, 16);
        if (lane == 0) y2s[row] = s;
    }

    // ---- convert W + per-k stats from registers ---------------------------
#pragma unroll
    for (int i = 0; i < 2; i++) {
        int row = 2 * wid + 32 * i + (lane >> 4);
        int c4  = lane & 15;
        uint2 hi, lo;
        cvt4t(Wv0[i], hi, lo);
        uint32_t off = (uint32_t)(row * ROW_BYTES + c4 * 8);
        *(uint2*)(smem + OFF_WHI + off) = hi;
        *(uint2*)(smem + OFF_WLO + off) = lo;
        cvt4t(Wv1[i], hi, lo);
        *(uint2*)(smem + OFF_WHI + off + 128) = hi;
        *(uint2*)(smem + OFF_WLO + off + 128) = lo;

        float4 a = Wv0[i], b = Wv1[i];
        float s = fmaf(a.x, a.x, fmaf(a.y, a.y, fmaf(a.z, a.z, a.w * a.w)));
        s = fmaf(b.x, b.x, fmaf(b.y, b.y, fmaf(b.z, b.z, fmaf(b.w, b.w, s))));
        float q0 = __shfl_xor_sync(0xffffffffu, a.x, 16);
        float q1 = __shfl_xor_sync(0xffffffffu, a.y, 16);
        float q2 = __shfl_xor_sync(0xffffffffu, a.z, 16);
        float q3 = __shfl_xor_sync(0xffffffffu, a.w, 16);
        float r0 = __shfl_xor_sync(0xffffffffu, b.x, 16);
        float r1 = __shfl_xor_sync(0xffffffffu, b.y, 16);
        float r2 = __shfl_xor_sync(0xffffffffu, b.z, 16);
        float r3 = __shfl_xor_sync(0xffffffffu, b.w, 16);
        float pa = fmaf(a.x, q0, fmaf(a.y, q1, fmaf(a.z, q2, a.w * q3)));
        pa = fmaf(b.x, r0, fmaf(b.y, r1, fmaf(b.z, r2, fmaf(b.w, r3, pa))));
        s  += __shfl_xor_sync(0xffffffffu, s, 1);
        s  += __shfl_xor_sync(0xffffffffu, s, 2);
        s  += __shfl_xor_sync(0xffffffffu, s, 4);
        s  += __shfl_xor_sync(0xffffffffu, s, 8);
        pa += __shfl_xor_sync(0xffffffffu, pa, 1);
        pa += __shfl_xor_sync(0xffffffffu, pa, 2);
        pa += __shfl_xor_sync(0xffffffffu, pa, 4);
        pa += __shfl_xor_sync(0xffffffffu, pa, 8);
        float s_opp = __shfl_xor_sync(0xffffffffu, s, 16);   // a2 -> low lanes
        if (lane == 0) {
            int k = wid + 16 * i;
            float p2 = s, a2 = s_opp;
            float an = fmaxf(sqrtf(a2), MIN_NORM);
            kst[k] = make_float4(p2, pa, 1.f - p2, 2.f * an);
        }
    }
    __syncthreads();

    // ---- warp tiling: 16 warps, warp tile 32 rows x 16 W-cols -------------
    const int wm = wid & 3;
    const int wn = wid >> 2;
    const int rm = wm * 32;
    const int cn = wn * 16;

    const int a_row = lane & 15;
    const int a_kh  = (lane >> 4) * 8;
    const int b_g   = lane >> 3;
    const int b_row = lane & 7;
    const int b_joff = (b_g >> 1);
    const int b_kh  = (b_g & 1) * 8;

    float acc[2][2][4];
#pragma unroll
    for (int ma = 0; ma < 2; ma++)
#pragma unroll
        for (int j = 0; j < 2; j++)
#pragma unroll
            for (int q = 0; q < 4; q++) acc[ma][j][q] = 0.f;

#pragma unroll
    for (int ks = 0; ks < 8; ks++) {
        const int kk = ks * 16;
        uint32_t Ahi[2][4], Alo[2][4], Bhi[2][2], Blo[2][2];
#pragma unroll
        for (int ma = 0; ma < 2; ma++) {
            uint32_t aoff = (uint32_t)((rm + ma * 16 + a_row) * ROW_BYTES
                                       + (kk + a_kh) * 2);
            ldsm_x4(Ahi[ma], sb + OFF_XHI + aoff);
            ldsm_x4(Alo[ma], sb + OFF_XLO + aoff);
        }
        {
            uint32_t boff = (uint32_t)((cn + b_joff * 8 + b_row) * ROW_BYTES
                                       + (kk + b_kh) * 2);
            uint32_t r[4];
            ldsm_x4(r, sb + OFF_WHI + boff);
            Bhi[0][0] = r[0]; Bhi[0][1] = r[1];
            Bhi[1][0] = r[2]; Bhi[1][1] = r[3];
            ldsm_x4(r, sb + OFF_WLO + boff);
            Blo[0][0] = r[0]; Blo[0][1] = r[1];
            Blo[1][0] = r[2]; Blo[1][1] = r[3];
        }
#pragma unroll
        for (int ma = 0; ma < 2; ma++) {
#pragma unroll
            for (int j = 0; j < 2; j++) {
                mma_bf16(acc[ma][j], Ahi[ma], Bhi[j]);
                mma_bf16(acc[ma][j], Ahi[ma], Blo[j]);
                mma_bf16(acc[ma][j], Alo[ma], Bhi[j]);
            }
        }
    }

    // ---- epilogue ----------------------------------------------------------
    const int l4 = lane >> 2;
    const int lm = lane & 3;
#pragma unroll
    for (int ma = 0; ma < 2; ma++) {
        const int r0 = rm + ma * 16 + l4;
        const int r1 = r0 + 8;
        const float y20 = y2s[r0];
        const float y21 = y2s[r1];
        float* o0 = out + (size_t)(bb + r0) * K_COLS + kb;
        float* o1 = out + (size_t)(bb + r1) * K_COLS + kb;
#pragma unroll
        for (int j = 0; j < 2; j++) {
            const int kl = wn * 8 + j * 4 + lm;
            const float4 kc = kst[kl];
            o0[kl] = mobius_epi(acc[ma][j][0], acc[ma][j][1], y20, kc);
            o1[kl] = mobius_epi(acc[ma][j][2], acc[ma][j][3], y21, kc);
        }
    }
}

// ---------------------------------------------------------------------------
extern "C" void kernel_launch(void* const* d_in, const int* in_sizes, int n_in,
                              void* d_out, int out_size) {
    const float* x = (const float*)d_in[0];   // (4096, 128)
    const float* p = (const float*)d_in[1];   // (256, 128)
    const float* a = (const float*)d_in[2];   // (256, 128)
    float* out = (float*)d_out;               // (4096, 256)

    cudaFuncSetAttribute(mobius_mlr_mma_kernel,
                         cudaFuncAttributeMaxDynamicSharedMemorySize, SMEM_BYTES);

    dim3 grid(K_COLS / BKH, B_ROWS / BM);     // (8, 32) = 256 CTAs, 2/SM
    mobius_mlr_mma_kernel<<<grid, THREADS, SMEM_BYTES>>>(x, p, a, out);
}